// round 7
// baseline (speedup 1.0000x reference)
#include <cuda_runtime.h>
#include <cstddef>
#include <cstdint>

// Problem constants
#define BB 16      // batch
#define TT 2048    // text len
#define EE 768     // embed dim
#define E4 (EE/4)  // 192 float4 per row
#define SS 32      // num sentences
#define LL 64      // max sent len
#define NT 128     // t-chunks for pooling pass
#define TCH (TT / NT)   // 16 timesteps per chunk
#define JC 8       // rows (j) per gather block

// Scratch (no device allocation allowed -> __device__ globals)
// Partial sums: [BB][NT][2 halves][EE] floats = 12.6MB
__device__ float4 g_partial4[BB * NT * 2 * E4];
__device__ int    g_start[BB * SS];
__device__ int    g_len[BB * SS];

// 256-bit load with L2 evict_last hint (sm_103 requires v8.b32 for this hint).
// Pins input lines in L2 so the gather pass (same 100.7MB < 126MB L2) hits L2.
struct F8 { float v[8]; };
__device__ __forceinline__ F8 ld256_evict_last(const float* p) {
    F8 r;
    uint32_t a,b,c,d,e,f,g,h;
    asm volatile("ld.global.L2::evict_last.v8.b32 {%0,%1,%2,%3,%4,%5,%6,%7}, [%8];"
                 : "=r"(a),"=r"(b),"=r"(c),"=r"(d),
                   "=r"(e),"=r"(f),"=r"(g),"=r"(h)
                 : "l"(p));
    r.v[0]=__uint_as_float(a); r.v[1]=__uint_as_float(b);
    r.v[2]=__uint_as_float(c); r.v[3]=__uint_as_float(d);
    r.v[4]=__uint_as_float(e); r.v[5]=__uint_as_float(f);
    r.v[6]=__uint_as_float(g); r.v[7]=__uint_as_float(h);
    return r;
}

// ---------------------------------------------------------------------------
// Kernel 1: streaming partial mean-pool over T with 256-bit evict_last loads.
// grid = BB*NT = 2048 blocks, 192 threads.
// Thread layout: half = tid/96 (time parity), col = tid%96 (32B chunk of row).
// Each thread: 8 independent LDG.E.256 over timesteps {half, half+2, ...}.
// Partial stored at row (b*NT + c)*2 + half.
// ---------------------------------------------------------------------------
__global__ __launch_bounds__(192) void k_pool(const float* __restrict__ in) {
    const int blk = blockIdx.x;
    const int b = blk >> 7;          // / NT
    const int c = blk & (NT - 1);    // % NT
    const int tid = threadIdx.x;
    const int half = tid / 96;       // 0..1
    const int col = tid - half * 96; // 0..95 (8-float chunk)

    const float* base = in + ((size_t)b * TT + (size_t)c * TCH + half) * EE + col * 8;

    float a0[8], a1[8];
#pragma unroll
    for (int k = 0; k < 8; k++) { a0[k] = 0.f; a1[k] = 0.f; }

#pragma unroll
    for (int t = 0; t < TCH; t += 4) {   // this thread covers t+half, t+2+half
        F8 u = ld256_evict_last(base + (size_t)t * EE);
        F8 w = ld256_evict_last(base + (size_t)(t + 2) * EE);
#pragma unroll
        for (int k = 0; k < 8; k++) { a0[k] += u.v[k]; a1[k] += w.v[k]; }
    }

    float4 s0, s1;
    s0.x = a0[0] + a1[0]; s0.y = a0[1] + a1[1];
    s0.z = a0[2] + a1[2]; s0.w = a0[3] + a1[3];
    s1.x = a0[4] + a1[4]; s1.y = a0[5] + a1[5];
    s1.z = a0[6] + a1[6]; s1.w = a0[7] + a1[7];

    float4* out = g_partial4 + (size_t)((b * NT + c) * 2 + half) * E4 + col * 2;
    out[0] = s0;
    out[1] = s1;
}

// ---------------------------------------------------------------------------
// Kernel 2: finish mean + tiny GEMV + exact index math (matches reference):
//   start_off = (int)clip(off_s, 0, 63); end_off = (int)clip(off_{s+32},0,63)
//   start = clip(s*64+start_off, 0, T-L); end = clip(s*64+64+end_off, start, T)
// grid = BB blocks, 512 threads.
//  Phase A: 384 threads, 256 partial rows split 2x (128-load chains) -> pooled.
//  Phase B: 512 threads = 64 cols x 8 e-segments of 96; shared reduce.
// ---------------------------------------------------------------------------
__global__ __launch_bounds__(512) void k_idx(const float* __restrict__ W,
                                             const float* __restrict__ bias) {
    const int b = blockIdx.x;
    const int tid = threadIdx.x;
    __shared__ float pooled[EE];
    __shared__ float4 pA[2 * E4];
    __shared__ float red[8][2 * SS];

    const int NROW = NT * 2;  // 256 partial rows per batch
    if (tid < 2 * E4) {
        const int g = tid / E4;          // 0..1 (row half)
        const int e4 = tid - g * E4;     // 0..191
        const float4* p = g_partial4 + ((size_t)b * NROW + (size_t)g * (NROW / 2)) * E4 + e4;
        float4 a0 = make_float4(0.f, 0.f, 0.f, 0.f);
        float4 a1 = make_float4(0.f, 0.f, 0.f, 0.f);
#pragma unroll 8
        for (int c = 0; c < NROW / 2; c += 2) {
            float4 v0 = p[(size_t)c * E4];
            float4 v1 = p[(size_t)(c + 1) * E4];
            a0.x += v0.x; a0.y += v0.y; a0.z += v0.z; a0.w += v0.w;
            a1.x += v1.x; a1.y += v1.y; a1.z += v1.z; a1.w += v1.w;
        }
        float4 s;
        s.x = a0.x + a1.x; s.y = a0.y + a1.y; s.z = a0.z + a1.z; s.w = a0.w + a1.w;
        pA[tid] = s;
    }
    __syncthreads();
    if (tid < E4) {
        const float inv = 1.0f / (float)TT;
        float4 u = pA[tid], w = pA[E4 + tid];
        pooled[4 * tid + 0] = (u.x + w.x) * inv;
        pooled[4 * tid + 1] = (u.y + w.y) * inv;
        pooled[4 * tid + 2] = (u.z + w.z) * inv;
        pooled[4 * tid + 3] = (u.w + w.w) * inv;
    }
    __syncthreads();

    // Phase B: col = tid & 63, segment g = tid >> 6 (0..7), 96 elems each.
    {
        const int col = tid & (2 * SS - 1);
        const int g = tid >> 6;
        float acc = 0.f;
        const int e0 = g * 96;
#pragma unroll 8
        for (int e = e0; e < e0 + 96; e++)
            acc = fmaf(pooled[e], W[e * (2 * SS) + col], acc);
        red[g][col] = acc;
    }
    __syncthreads();

    if (tid < SS) {
        const int s = tid;
        float off1 = bias[s], off2 = bias[s + SS];
#pragma unroll
        for (int g = 0; g < 8; g++) { off1 += red[g][s]; off2 += red[g][s + SS]; }

        const int so = (int)fminf(fmaxf(off1, 0.f), (float)(LL - 1));
        const int eo = (int)fminf(fmaxf(off2, 0.f), (float)(LL - 1));

        const int basei = s * LL;
        int start = basei + so;
        if (start > TT - LL) start = TT - LL;
        if (start < 0) start = 0;
        int end = basei + LL + eo;
        if (end < start) end = start;
        if (end > TT) end = TT;

        g_start[b * SS + s] = start;
        g_len[b * SS + s]   = end - start;
    }
}

// ---------------------------------------------------------------------------
// Kernel 3: vectorized gather+pad.
// grid = BB*SS*(LL/JC) = 4096 blocks, 192 threads.
// 8 independent LDG.128 in flight before any store; reads should hit L2
// (input pinned evict_last by k_pool); __stcs output stores are evict_first
// so they victimize themselves, not the input.
// ---------------------------------------------------------------------------
__global__ __launch_bounds__(192) void k_gather(const float4* __restrict__ in,
                                                float4* __restrict__ out) {
    const int idx = blockIdx.x;
    const int jc = idx & (LL / JC - 1);          // 0..7
    const int s  = (idx >> 3) & (SS - 1);        // 0..31
    const int b  = idx >> 8;                     // 0..15
    const int tid = threadIdx.x;                 // 0..191

    const int start = g_start[b * SS + s];
    const int len   = g_len[b * SS + s];

    const float4* src = in + ((size_t)b * TT + (size_t)start) * E4 + tid;
    float4* dst = out + ((size_t)(b * SS + s) * LL) * E4 + tid;

    const int j0 = jc * JC;
    float4 v[JC];
#pragma unroll
    for (int jj = 0; jj < JC; jj++) {
        const int j = j0 + jj;
        v[jj] = (j < len) ? src[(size_t)j * E4]
                          : make_float4(0.f, 0.f, 0.f, 0.f);
    }
#pragma unroll
    for (int jj = 0; jj < JC; jj++)
        __stcs(&dst[(size_t)(j0 + jj) * E4], v[jj]);
}

// ---------------------------------------------------------------------------
// Entry point. Inputs (metadata order): inputs f32 [B,T,E], W f32 [E,2S],
// b f32 [2S]. Output f32 [B,S,L,E].
// ---------------------------------------------------------------------------
extern "C" void kernel_launch(void* const* d_in, const int* in_sizes, int n_in,
                              void* d_out, int out_size) {
    const float* in   = (const float*)d_in[0];
    const float* W    = (const float*)d_in[1];
    const float* bias = (const float*)d_in[2];
    float4* out       = (float4*)d_out;

    k_pool<<<BB * NT, 192>>>(in);
    k_idx<<<BB, 512>>>(W, bias);
    k_gather<<<BB * SS * (LL / JC), 192>>>((const float4*)in, out);
}

// round 10
// speedup vs baseline: 1.1039x; 1.1039x over previous
#include <cuda_runtime.h>
#include <cstddef>

// Problem constants
#define BB 16      // batch
#define TT 2048    // text len
#define EE 768     // embed dim
#define E4 (EE/4)  // 192 float4 per row
#define SS 32      // num sentences
#define LL 64      // max sent len
#define NT 128     // t-chunks for pooling pass
#define TCH (TT / NT)   // 16 timesteps per chunk
#define JC 8       // rows (j) per gather block

// Scratch (no device allocation allowed -> __device__ globals)
__device__ float4 g_partial4[BB * NT * E4];  // 6.3MB partial sums (b, chunk, e4)
__device__ int    g_start[BB * SS];
__device__ int    g_len[BB * SS];

// ---------------------------------------------------------------------------
// Kernel 1: streaming partial mean-pool over T. float4, plain loads
// (evict hints measured as a regression in R7 -> removed).
// grid = BB*NT = 2048 blocks, 192 threads; thread owns one float4 column.
// TCH=16: 16 independent LDG.128 per thread, 4 accumulators (4-deep chains).
// ---------------------------------------------------------------------------
__global__ __launch_bounds__(192) void k_pool(const float4* __restrict__ in) {
    const int blk = blockIdx.x;
    const int b = blk >> 7;          // / NT
    const int c = blk & (NT - 1);    // % NT
    const int e4 = threadIdx.x;      // 0..191

    const float4* base = in + ((size_t)b * TT + (size_t)c * TCH) * E4 + e4;

    float4 a0 = make_float4(0.f, 0.f, 0.f, 0.f);
    float4 a1 = make_float4(0.f, 0.f, 0.f, 0.f);
    float4 a2 = make_float4(0.f, 0.f, 0.f, 0.f);
    float4 a3 = make_float4(0.f, 0.f, 0.f, 0.f);
#pragma unroll
    for (int t = 0; t < TCH; t += 4) {
        float4 v0 = base[(size_t)(t + 0) * E4];
        float4 v1 = base[(size_t)(t + 1) * E4];
        float4 v2 = base[(size_t)(t + 2) * E4];
        float4 v3 = base[(size_t)(t + 3) * E4];
        a0.x += v0.x; a0.y += v0.y; a0.z += v0.z; a0.w += v0.w;
        a1.x += v1.x; a1.y += v1.y; a1.z += v1.z; a1.w += v1.w;
        a2.x += v2.x; a2.y += v2.y; a2.z += v2.z; a2.w += v2.w;
        a3.x += v3.x; a3.y += v3.y; a3.z += v3.z; a3.w += v3.w;
    }
    float4 s;
    s.x = (a0.x + a1.x) + (a2.x + a3.x);
    s.y = (a0.y + a1.y) + (a2.y + a3.y);
    s.z = (a0.z + a1.z) + (a2.z + a3.z);
    s.w = (a0.w + a1.w) + (a2.w + a3.w);
    g_partial4[(size_t)(b * NT + c) * E4 + e4] = s;
}

// ---------------------------------------------------------------------------
// Kernel 2: finish mean + tiny GEMV + exact index math (matches reference):
//   start_off = (int)clip(off_s, 0, 63); end_off = (int)clip(off_{s+32},0,63)
//   start = clip(s*64+start_off, 0, T-L); end = clip(s*64+64+end_off, start, T)
// grid = BB blocks, 512 threads.
//  Phase A: 384 threads, chunk-dim split 2x (64-row chains) -> pooled[768].
//  Phase B: 512 threads = 64 cols x 8 e-segments of 96; shared reduce.
// ---------------------------------------------------------------------------
__global__ __launch_bounds__(512) void k_idx(const float* __restrict__ W,
                                             const float* __restrict__ bias) {
    const int b = blockIdx.x;
    const int tid = threadIdx.x;
    __shared__ float pooled[EE];
    __shared__ float4 pA[2 * E4];
    __shared__ float red[8][2 * SS];

    if (tid < 2 * E4) {
        const int g = tid / E4;          // 0..1 (chunk half)
        const int e4 = tid - g * E4;     // 0..191
        const float4* p = g_partial4 + ((size_t)b * NT + (size_t)g * (NT / 2)) * E4 + e4;
        float4 a0 = make_float4(0.f, 0.f, 0.f, 0.f);
        float4 a1 = make_float4(0.f, 0.f, 0.f, 0.f);
#pragma unroll 8
        for (int c = 0; c < NT / 2; c += 2) {
            float4 v0 = p[(size_t)c * E4];
            float4 v1 = p[(size_t)(c + 1) * E4];
            a0.x += v0.x; a0.y += v0.y; a0.z += v0.z; a0.w += v0.w;
            a1.x += v1.x; a1.y += v1.y; a1.z += v1.z; a1.w += v1.w;
        }
        float4 s;
        s.x = a0.x + a1.x; s.y = a0.y + a1.y; s.z = a0.z + a1.z; s.w = a0.w + a1.w;
        pA[tid] = s;
    }
    __syncthreads();
    if (tid < E4) {
        const float inv = 1.0f / (float)TT;
        float4 u = pA[tid], w = pA[E4 + tid];
        pooled[4 * tid + 0] = (u.x + w.x) * inv;
        pooled[4 * tid + 1] = (u.y + w.y) * inv;
        pooled[4 * tid + 2] = (u.z + w.z) * inv;
        pooled[4 * tid + 3] = (u.w + w.w) * inv;
    }
    __syncthreads();

    // Phase B: col = tid & 63, segment g = tid >> 6 (0..7), 96 elems each.
    {
        const int col = tid & (2 * SS - 1);
        const int g = tid >> 6;
        float acc = 0.f;
        const int e0 = g * 96;
#pragma unroll 8
        for (int e = e0; e < e0 + 96; e++)
            acc = fmaf(pooled[e], W[e * (2 * SS) + col], acc);
        red[g][col] = acc;
    }
    __syncthreads();

    if (tid < SS) {
        const int s = tid;
        float off1 = bias[s], off2 = bias[s + SS];
#pragma unroll
        for (int g = 0; g < 8; g++) { off1 += red[g][s]; off2 += red[g][s + SS]; }

        const int so = (int)fminf(fmaxf(off1, 0.f), (float)(LL - 1));
        const int eo = (int)fminf(fmaxf(off2, 0.f), (float)(LL - 1));

        const int basei = s * LL;
        int start = basei + so;
        if (start > TT - LL) start = TT - LL;
        if (start < 0) start = 0;
        int end = basei + LL + eo;
        if (end < start) end = start;
        if (end > TT) end = TT;

        g_start[b * SS + s] = start;
        g_len[b * SS + s]   = end - start;
    }
}

// ---------------------------------------------------------------------------
// Kernel 3: vectorized gather+pad (identical to the best-measured R5 config).
// grid = BB*SS*(LL/JC) = 4096 blocks, 192 threads.
// 8 independent LDG.128 in flight before any store, then 8 streaming stores.
// ---------------------------------------------------------------------------
__global__ __launch_bounds__(192) void k_gather(const float4* __restrict__ in,
                                                float4* __restrict__ out) {
    const int idx = blockIdx.x;
    const int jc = idx & (LL / JC - 1);          // 0..7
    const int s  = (idx >> 3) & (SS - 1);        // 0..31
    const int b  = idx >> 8;                     // 0..15
    const int tid = threadIdx.x;                 // 0..191

    const int start = g_start[b * SS + s];
    const int len   = g_len[b * SS + s];

    const float4* src = in + ((size_t)b * TT + (size_t)start) * E4 + tid;
    float4* dst = out + ((size_t)(b * SS + s) * LL) * E4 + tid;

    const int j0 = jc * JC;
    float4 v[JC];
#pragma unroll
    for (int jj = 0; jj < JC; jj++) {
        const int j = j0 + jj;
        v[jj] = (j < len) ? src[(size_t)j * E4]
                          : make_float4(0.f, 0.f, 0.f, 0.f);
    }
#pragma unroll
    for (int jj = 0; jj < JC; jj++)
        __stcs(&dst[(size_t)(j0 + jj) * E4], v[jj]);
}

// ---------------------------------------------------------------------------
// Entry point. Inputs (metadata order): inputs f32 [B,T,E], W f32 [E,2S],
// b f32 [2S]. Output f32 [B,S,L,E].
// ---------------------------------------------------------------------------
extern "C" void kernel_launch(void* const* d_in, const int* in_sizes, int n_in,
                              void* d_out, int out_size) {
    const float4* in  = (const float4*)d_in[0];
    const float* W    = (const float*)d_in[1];
    const float* bias = (const float*)d_in[2];
    float4* out       = (float4*)d_out;

    k_pool<<<BB * NT, 192>>>(in);
    k_idx<<<BB, 512>>>(W, bias);
    k_gather<<<BB * SS * (LL / JC), 192>>>(in, out);
}